// round 6
// baseline (speedup 1.0000x reference)
#include <cuda_runtime.h>
#include <cstdint>

#define CSIZE 8
#define NCTA  128
#define NT    256
#define RWS   32
#define LSEQ  1000
#define HST   33            // hT row stride in floats (odd => conflict-free)
#define HTSZ  (128*HST)     // floats per hT buffer

// float-index offsets into dynamic smem
#define FO_W1   0           // [64][128]
#define FO_W2I  8192
#define FO_W2H  16384
#define FO_HT1  24576       // [2][128][HST]
#define FO_HT2  33024       // [128][HST]
#define FO_BS1  39424       // [64]
#define FO_BS2  39488
#define FO_WI1  39552
#define FO_WL   39616       // [128]
#define FO_XS   39744       // [32]
#define GB_BYTE 159104      // ull[64*17]
#define SMEM_SZ 167808

typedef unsigned long long ull;

__device__ __forceinline__ ull ffma2(ull a, ull b, ull c) {
    ull d;
    asm("fma.rn.f32x2 %0, %1, %2, %3;" : "=l"(d) : "l"(a), "l"(b), "l"(c));
    return d;
}
__device__ __forceinline__ ull add2(ull a, ull b) {
    ull d;
    asm("add.rn.f32x2 %0, %1, %2;" : "=l"(d) : "l"(a), "l"(b));
    return d;
}
__device__ __forceinline__ ull packf2(float lo, float hi) {
    ull d;
    asm("mov.b64 %0, {%1, %2};" : "=l"(d) : "f"(lo), "f"(hi));
    return d;
}
__device__ __forceinline__ ull repf(float v) {
    ull d;
    asm("mov.b64 %0, {%1, %1};" : "=l"(d) : "f"(v));
    return d;
}
__device__ __forceinline__ float flo(ull v) { return __uint_as_float((unsigned)v); }
__device__ __forceinline__ float fhi(ull v) { return __uint_as_float((unsigned)(v >> 32)); }

__device__ __forceinline__ float tanhx(float v) {
    float r; asm("tanh.approx.f32 %0, %1;" : "=f"(r) : "f"(v)); return r;
}
__device__ __forceinline__ float sigx(float v) { return fmaf(tanhx(0.5f * v), 0.5f, 0.5f); }

__device__ __forceinline__ uint32_t smem_u32(const void* p) {
    uint32_t a;
    asm("{ .reg .u64 t; cvta.to.shared.u64 t, %1; cvt.u32.u64 %0, t; }" : "=r"(a) : "l"(p));
    return a;
}
__device__ __forceinline__ uint32_t ctarank() {
    uint32_t r; asm("mov.u32 %0, %%cluster_ctarank;" : "=r"(r)); return r;
}
__device__ __forceinline__ void st_cluster_f32(uint32_t addr, uint32_t rank, float v) {
    asm volatile("{ .reg .u32 ra; mapa.shared::cluster.u32 ra, %0, %1;"
                 " st.shared::cluster.f32 [ra], %2; }"
                 :: "r"(addr), "r"(rank), "f"(v) : "memory");
}
__device__ __forceinline__ void cl_sync() {
    asm volatile("barrier.cluster.arrive.aligned;" ::: "memory");
    asm volatile("barrier.cluster.wait.aligned;" ::: "memory");
}

// exchange-reduce 32 accs across 32 lanes; lane l ends with logical acc l in A[0]
#define REDUCE5(A) do {                                                        \
    _Pragma("unroll") for (int s = 0; s < 32; s += 2)                          \
        A[s] = add2(A[s], __shfl_xor_sync(0xffffffffu, A[s + 1], 16));         \
    _Pragma("unroll") for (int s = 0; s < 32; s += 4)                          \
        A[s] = add2(A[s], __shfl_xor_sync(0xffffffffu, A[s + 2], 8));          \
    _Pragma("unroll") for (int s = 0; s < 32; s += 8)                          \
        A[s] = add2(A[s], __shfl_xor_sync(0xffffffffu, A[s + 4], 4));          \
    _Pragma("unroll") for (int s = 0; s < 32; s += 16)                         \
        A[s] = add2(A[s], __shfl_xor_sync(0xffffffffu, A[s + 8], 2));          \
    A[0] = add2(A[0], __shfl_xor_sync(0xffffffffu, A[16], 1));                 \
} while (0)

__global__ void __launch_bounds__(NT, 1) __cluster_dims__(CSIZE, 1, 1)
lstm8(const float* __restrict__ x,
      const float* __restrict__ w_ih1, const float* __restrict__ w_hh1,
      const float* __restrict__ b_ih1, const float* __restrict__ b_hh1,
      const float* __restrict__ w_ih2, const float* __restrict__ w_hh2,
      const float* __restrict__ b_ih2, const float* __restrict__ b_hh2,
      const float* __restrict__ w_lin, const float* __restrict__ b_lin,
      float* __restrict__ out)
{
    extern __shared__ char sm[];
    float* SF  = (float*)sm;
    float* W1s = SF + FO_W1;
    float* W2I = SF + FO_W2I;
    float* W2H = SF + FO_W2H;
    float* HT1 = SF + FO_HT1;
    float* HT2 = SF + FO_HT2;
    float* BS1 = SF + FO_BS1;
    float* BS2 = SF + FO_BS2;
    float* WI1 = SF + FO_WI1;
    float* WL  = SF + FO_WL;
    float* XS  = SF + FO_XS;
    ull*   GBu = (ull*)(sm + GB_BYTE);

    const int tid  = threadIdx.x;
    const uint32_t rank = ctarank();
    const int clus = blockIdx.x >> 3;
    const int row0 = clus * RWS;
    const int UB   = rank * 16;

    const int w    = tid >> 5;
    const int ln   = tid & 31;
    const int l2   = ln >> 2;       // bits [4:2]
    const int llo  = ln & 3;        // bits [1:0]
    // permuted pair columns: pc[i2] = 2*(llo ^ rev2(i2)), rev2 = {0,2,1,3}
    const int pc0 = 2 * (llo ^ 0);
    const int pc1 = 2 * (llo ^ 2);
    const int pc2 = 2 * (llo ^ 1);
    const int pc3 = 2 * (llo ^ 3);

    // ---- init: weights -> SMEM (coalesced) ----
    for (int idx = tid; idx < 64 * 128; idx += NT) {
        int j = idx >> 7, k = idx & 127;
        int gj = ((j >> 4) << 7) + UB + (j & 15);
        W1s[idx] = w_hh1[gj * 128 + k];
        W2I[idx] = w_ih2[gj * 128 + k];
        W2H[idx] = w_hh2[gj * 128 + k];
    }
    for (int idx = tid; idx < 64; idx += NT) {
        int gj = ((idx >> 4) << 7) + UB + (idx & 15);
        BS1[idx] = b_ih1[gj] + b_hh1[gj];
        BS2[idx] = b_ih2[gj] + b_hh2[gj];
        WI1[idx] = w_ih1[gj];
    }
    for (int idx = tid; idx < 128; idx += NT) WL[idx] = w_lin[idx];
    for (int idx = tid; idx < 2 * HTSZ; idx += NT) HT1[idx] = 0.0f;
    for (int idx = tid; idx < HTSZ; idx += NT) HT2[idx] = 0.0f;

    const int au = tid >> 4;        // act: unit-local 0..15
    const int ap = tid & 15;        // act: batch pair 0..15
    float c1e = 0.f, c1o = 0.f, c2e = 0.f, c2o = 0.f;
    const float blin = b_lin[0];
    const uint32_t smb = smem_u32(sm);
    const int hoff = ln * HST;      // thread's base k-row offset

    __syncthreads();
    cl_sync();

    int p = 0;
    for (int t = 0; t < LSEQ; t++) {
        const int np = p ^ 1;
        float xv = 0.0f;
        if (tid < 32) xv = x[(row0 + tid) * LSEQ + t];

        // ======== mv1: gates1 = h1[p] @ W1^T ========
        {
            ull wr[8][4];
#pragma unroll
            for (int i = 0; i < 8; i++) {
                int ri = 8 * w + (l2 ^ (((i & 1) << 2) | (i & 2) | ((i & 4) >> 2)));
#pragma unroll
                for (int kk = 0; kk < 4; kk++)
                    wr[i][kk] = repf(W1s[ri * 128 + ln + 32 * kk]);
            }
            const float* h1p = HT1 + p * HTSZ + hoff;
#pragma unroll 1
            for (int q = 0; q < 4; q++) {
                ull A[32];
#pragma unroll
                for (int s = 0; s < 32; s++) A[s] = 0ull;
#pragma unroll
                for (int kk = 0; kk < 4; kk++) {
                    const float* hr = h1p + kk * (32 * HST) + 8 * q;
                    ull hv0 = packf2(hr[pc0], hr[pc0 + 1]);
                    ull hv1 = packf2(hr[pc1], hr[pc1 + 1]);
                    ull hv2 = packf2(hr[pc2], hr[pc2 + 1]);
                    ull hv3 = packf2(hr[pc3], hr[pc3 + 1]);
#pragma unroll
                    for (int s = 0; s < 32; s++) {
                        ull hvv = (s < 8) ? hv0 : (s < 16) ? hv1 : (s < 24) ? hv2 : hv3;
                        A[s] = ffma2(wr[s & 7][kk], hvv, A[s]);
                    }
                }
                REDUCE5(A);
                GBu[(8 * w + l2) * 17 + 4 * q + llo] = A[0];
            }
        }
        if (tid < 32) XS[tid] = xv;
        __syncthreads();

        // ======== act1 ========
        {
            ull g0 = GBu[au * 17 + ap];
            ull g1 = GBu[(16 + au) * 17 + ap];
            ull g2 = GBu[(32 + au) * 17 + ap];
            ull g3 = GBu[(48 + au) * 17 + ap];
            float xe = XS[2 * ap], xo = XS[2 * ap + 1];
            float b0 = BS1[au], b1 = BS1[16 + au], b2 = BS1[32 + au], b3 = BS1[48 + au];
            float u0 = WI1[au], u1 = WI1[16 + au], u2 = WI1[32 + au], u3 = WI1[48 + au];
            float ie = sigx (fmaf(u0, xe, flo(g0) + b0)), io_ = sigx (fmaf(u0, xo, fhi(g0) + b0));
            float fe = sigx (fmaf(u1, xe, flo(g1) + b1)), fo_ = sigx (fmaf(u1, xo, fhi(g1) + b1));
            float ge = tanhx(fmaf(u2, xe, flo(g2) + b2)), go_ = tanhx(fmaf(u2, xo, fhi(g2) + b2));
            float oe = sigx (fmaf(u3, xe, flo(g3) + b3)), oo_ = sigx (fmaf(u3, xo, fhi(g3) + b3));
            c1e = fmaf(fe, c1e, ie * ge);
            c1o = fmaf(fo_, c1o, io_ * go_);
            float he = oe * tanhx(c1e), ho = oo_ * tanhx(c1o);
            uint32_t ad = smb + 4u * (FO_HT1 + np * HTSZ + (UB + au) * HST + 2 * ap);
#pragma unroll
            for (int pcr = 0; pcr < CSIZE; pcr++) {
                st_cluster_f32(ad, pcr, he);
                st_cluster_f32(ad + 4, pcr, ho);
            }
        }
        cl_sync();   // sync_a: h1[np] complete everywhere; h2(t-1) stores complete

        // ======== readout of step t-1 ========
        if (t > 0 && tid < 32) {
            float s = blin;
#pragma unroll 8
            for (int u = 0; u < 128; u++)
                s = fmaf(HT2[u * HST + tid], WL[u], s);
            out[(row0 + tid) * LSEQ + (t - 1)] = s;
        }

        // ======== mv2: gates2 = h1[np] @ W2I^T + h2 @ W2H^T ========
        {
            ull wi[8][4], wh[8][4];
#pragma unroll
            for (int i = 0; i < 8; i++) {
                int ri = 8 * w + (l2 ^ (((i & 1) << 2) | (i & 2) | ((i & 4) >> 2)));
#pragma unroll
                for (int kk = 0; kk < 4; kk++) {
                    wi[i][kk] = repf(W2I[ri * 128 + ln + 32 * kk]);
                    wh[i][kk] = repf(W2H[ri * 128 + ln + 32 * kk]);
                }
            }
            const float* h1n = HT1 + np * HTSZ + hoff;
            const float* h2p = HT2 + hoff;
#pragma unroll 1
            for (int q = 0; q < 4; q++) {
                ull A[32];
#pragma unroll
                for (int s = 0; s < 32; s++) A[s] = 0ull;
#pragma unroll
                for (int kk = 0; kk < 4; kk++) {
                    const float* hr = h1n + kk * (32 * HST) + 8 * q;
                    ull hv0 = packf2(hr[pc0], hr[pc0 + 1]);
                    ull hv1 = packf2(hr[pc1], hr[pc1 + 1]);
                    ull hv2 = packf2(hr[pc2], hr[pc2 + 1]);
                    ull hv3 = packf2(hr[pc3], hr[pc3 + 1]);
#pragma unroll
                    for (int s = 0; s < 32; s++) {
                        ull hvv = (s < 8) ? hv0 : (s < 16) ? hv1 : (s < 24) ? hv2 : hv3;
                        A[s] = ffma2(wi[s & 7][kk], hvv, A[s]);
                    }
                }
#pragma unroll
                for (int kk = 0; kk < 4; kk++) {
                    const float* hr = h2p + kk * (32 * HST) + 8 * q;
                    ull hv0 = packf2(hr[pc0], hr[pc0 + 1]);
                    ull hv1 = packf2(hr[pc1], hr[pc1 + 1]);
                    ull hv2 = packf2(hr[pc2], hr[pc2 + 1]);
                    ull hv3 = packf2(hr[pc3], hr[pc3 + 1]);
#pragma unroll
                    for (int s = 0; s < 32; s++) {
                        ull hvv = (s < 8) ? hv0 : (s < 16) ? hv1 : (s < 24) ? hv2 : hv3;
                        A[s] = ffma2(wh[s & 7][kk], hvv, A[s]);
                    }
                }
                REDUCE5(A);
                GBu[(8 * w + l2) * 17 + 4 * q + llo] = A[0];
            }
        }
        __syncthreads();

        // ======== act2 ========
        float h2e, h2o;
        {
            ull g0 = GBu[au * 17 + ap];
            ull g1 = GBu[(16 + au) * 17 + ap];
            ull g2 = GBu[(32 + au) * 17 + ap];
            ull g3 = GBu[(48 + au) * 17 + ap];
            float b0 = BS2[au], b1 = BS2[16 + au], b2 = BS2[32 + au], b3 = BS2[48 + au];
            float ie = sigx (flo(g0) + b0), io_ = sigx (fhi(g0) + b0);
            float fe = sigx (flo(g1) + b1), fo_ = sigx (fhi(g1) + b1);
            float ge = tanhx(flo(g2) + b2), go_ = tanhx(fhi(g2) + b2);
            float oe = sigx (flo(g3) + b3), oo_ = sigx (fhi(g3) + b3);
            c2e = fmaf(fe, c2e, ie * ge);
            c2o = fmaf(fo_, c2o, io_ * go_);
            h2e = oe * tanhx(c2e);
            h2o = oo_ * tanhx(c2o);
        }
        cl_sync();   // sync_b: all mv2/readout reads of old h2 done
        {
            uint32_t ad = smb + 4u * (FO_HT2 + (UB + au) * HST + 2 * ap);
#pragma unroll
            for (int pcr = 0; pcr < CSIZE; pcr++) {
                st_cluster_f32(ad, pcr, h2e);
                st_cluster_f32(ad + 4, pcr, h2o);
            }
        }
        p = np;
    }

    // final readout (t = LSEQ-1)
    cl_sync();
    if (tid < 32) {
        float s = blin;
#pragma unroll 8
        for (int u = 0; u < 128; u++)
            s = fmaf(HT2[u * HST + tid], WL[u], s);
        out[(row0 + tid) * LSEQ + (LSEQ - 1)] = s;
    }
}

extern "C" void kernel_launch(void* const* d_in, const int* in_sizes, int n_in,
                              void* d_out, int out_size) {
    cudaFuncSetAttribute(lstm8, cudaFuncAttributeMaxDynamicSharedMemorySize, SMEM_SZ);

    const float* x     = (const float*)d_in[0];
    const float* w_ih1 = (const float*)d_in[1];
    const float* w_hh1 = (const float*)d_in[2];
    const float* b_ih1 = (const float*)d_in[3];
    const float* b_hh1 = (const float*)d_in[4];
    const float* w_ih2 = (const float*)d_in[5];
    const float* w_hh2 = (const float*)d_in[6];
    const float* b_ih2 = (const float*)d_in[7];
    const float* b_hh2 = (const float*)d_in[8];
    const float* w_lin = (const float*)d_in[9];
    const float* b_lin = (const float*)d_in[10];
    float* out = (float*)d_out;

    lstm8<<<NCTA, NT, SMEM_SZ>>>(x, w_ih1, w_hh1, b_ih1, b_hh1,
                                 w_ih2, w_hh2, b_ih2, b_hh2,
                                 w_lin, b_lin, out);
}

// round 7
// speedup vs baseline: 1.0003x; 1.0003x over previous
#include <cuda_runtime.h>
#include <cstdint>

#define CSIZE 8
#define NCTA  128
#define NT    256
#define RWS   32
#define LSEQ  1000
#define HST   33            // hT row stride in floats (odd => conflict-free)
#define HTSZ  (128*HST)     // floats per hT buffer

// float-index offsets into dynamic smem
#define FO_W1   0           // [64][128]
#define FO_W2I  8192
#define FO_W2H  16384
#define FO_HT1  24576       // [2][128][HST]
#define FO_HT2  33024       // [128][HST]
#define FO_BS1  39424       // [64]
#define FO_BS2  39488
#define FO_WI1  39552
#define FO_WL   39616       // [128]
#define FO_XS   39744       // [32]
#define GB_BYTE 159104      // ull[64*17]
#define SMEM_SZ 167808

typedef unsigned long long ull;

__device__ __forceinline__ ull ffma2(ull a, ull b, ull c) {
    ull d;
    asm("fma.rn.f32x2 %0, %1, %2, %3;" : "=l"(d) : "l"(a), "l"(b), "l"(c));
    return d;
}
__device__ __forceinline__ ull add2(ull a, ull b) {
    ull d;
    asm("add.rn.f32x2 %0, %1, %2;" : "=l"(d) : "l"(a), "l"(b));
    return d;
}
__device__ __forceinline__ ull packf2(float lo, float hi) {
    ull d;
    asm("mov.b64 %0, {%1, %2};" : "=l"(d) : "f"(lo), "f"(hi));
    return d;
}
__device__ __forceinline__ ull repf(float v) {
    ull d;
    asm("mov.b64 %0, {%1, %1};" : "=l"(d) : "f"(v));
    return d;
}
__device__ __forceinline__ float flo(ull v) { return __uint_as_float((unsigned)v); }
__device__ __forceinline__ float fhi(ull v) { return __uint_as_float((unsigned)(v >> 32)); }

__device__ __forceinline__ float tanhx(float v) {
    float r; asm("tanh.approx.f32 %0, %1;" : "=f"(r) : "f"(v)); return r;
}
__device__ __forceinline__ float sigx(float v) { return fmaf(tanhx(0.5f * v), 0.5f, 0.5f); }

__device__ __forceinline__ uint32_t smem_u32(const void* p) {
    uint32_t a;
    asm("{ .reg .u64 t; cvta.to.shared.u64 t, %1; cvt.u32.u64 %0, t; }" : "=r"(a) : "l"(p));
    return a;
}
__device__ __forceinline__ uint32_t ctarank() {
    uint32_t r; asm("mov.u32 %0, %%cluster_ctarank;" : "=r"(r)); return r;
}
__device__ __forceinline__ void st_cluster_f32(uint32_t addr, uint32_t rank, float v) {
    asm volatile("{ .reg .u32 ra; mapa.shared::cluster.u32 ra, %0, %1;"
                 " st.shared::cluster.f32 [ra], %2; }"
                 :: "r"(addr), "r"(rank), "f"(v) : "memory");
}
__device__ __forceinline__ void cl_sync() {
    asm volatile("barrier.cluster.arrive.aligned;" ::: "memory");
    asm volatile("barrier.cluster.wait.aligned;" ::: "memory");
}

// exchange-reduce 32 accs across 32 lanes; lane l ends with logical acc l in A[0]
#define REDUCE5(A) do {                                                        \
    _Pragma("unroll") for (int s = 0; s < 32; s += 2)                          \
        A[s] = add2(A[s], __shfl_xor_sync(0xffffffffu, A[s + 1], 16));         \
    _Pragma("unroll") for (int s = 0; s < 32; s += 4)                          \
        A[s] = add2(A[s], __shfl_xor_sync(0xffffffffu, A[s + 2], 8));          \
    _Pragma("unroll") for (int s = 0; s < 32; s += 8)                          \
        A[s] = add2(A[s], __shfl_xor_sync(0xffffffffu, A[s + 4], 4));          \
    _Pragma("unroll") for (int s = 0; s < 32; s += 16)                         \
        A[s] = add2(A[s], __shfl_xor_sync(0xffffffffu, A[s + 8], 2));          \
    A[0] = add2(A[0], __shfl_xor_sync(0xffffffffu, A[16], 1));                 \
} while (0)

__global__ void __launch_bounds__(NT, 1) __cluster_dims__(CSIZE, 1, 1)
lstm8(const float* __restrict__ x,
      const float* __restrict__ w_ih1, const float* __restrict__ w_hh1,
      const float* __restrict__ b_ih1, const float* __restrict__ b_hh1,
      const float* __restrict__ w_ih2, const float* __restrict__ w_hh2,
      const float* __restrict__ b_ih2, const float* __restrict__ b_hh2,
      const float* __restrict__ w_lin, const float* __restrict__ b_lin,
      float* __restrict__ out)
{
    extern __shared__ char sm[];
    float* SF  = (float*)sm;
    float* W1s = SF + FO_W1;
    float* W2I = SF + FO_W2I;
    float* W2H = SF + FO_W2H;
    float* HT1 = SF + FO_HT1;
    float* HT2 = SF + FO_HT2;
    float* BS1 = SF + FO_BS1;
    float* BS2 = SF + FO_BS2;
    float* WI1 = SF + FO_WI1;
    float* WL  = SF + FO_WL;
    float* XS  = SF + FO_XS;
    ull*   GBu = (ull*)(sm + GB_BYTE);

    const int tid  = threadIdx.x;
    const uint32_t rank = ctarank();
    const int clus = blockIdx.x >> 3;
    const int row0 = clus * RWS;
    const int UB   = rank * 16;

    const int w    = tid >> 5;
    const int ln   = tid & 31;
    const int l2   = ln >> 2;       // bits [4:2]
    const int llo  = ln & 3;        // bits [1:0]
    // permuted pair columns: pc[i2] = 2*(llo ^ rev2(i2)), rev2 = {0,2,1,3}
    const int pc0 = 2 * (llo ^ 0);
    const int pc1 = 2 * (llo ^ 2);
    const int pc2 = 2 * (llo ^ 1);
    const int pc3 = 2 * (llo ^ 3);

    // ---- init: weights -> SMEM (coalesced) ----
    for (int idx = tid; idx < 64 * 128; idx += NT) {
        int j = idx >> 7, k = idx & 127;
        int gj = ((j >> 4) << 7) + UB + (j & 15);
        W1s[idx] = w_hh1[gj * 128 + k];
        W2I[idx] = w_ih2[gj * 128 + k];
        W2H[idx] = w_hh2[gj * 128 + k];
    }
    for (int idx = tid; idx < 64; idx += NT) {
        int gj = ((idx >> 4) << 7) + UB + (idx & 15);
        BS1[idx] = b_ih1[gj] + b_hh1[gj];
        BS2[idx] = b_ih2[gj] + b_hh2[gj];
        WI1[idx] = w_ih1[gj];
    }
    for (int idx = tid; idx < 128; idx += NT) WL[idx] = w_lin[idx];
    for (int idx = tid; idx < 2 * HTSZ; idx += NT) HT1[idx] = 0.0f;
    for (int idx = tid; idx < HTSZ; idx += NT) HT2[idx] = 0.0f;

    const int au = tid >> 4;        // act: unit-local 0..15
    const int ap = tid & 15;        // act: batch pair 0..15
    float c1e = 0.f, c1o = 0.f, c2e = 0.f, c2o = 0.f;
    const float blin = b_lin[0];
    const uint32_t smb = smem_u32(sm);
    const int hoff = ln * HST;      // thread's base k-row offset

    __syncthreads();
    cl_sync();

    int p = 0;
    for (int t = 0; t < LSEQ; t++) {
        const int np = p ^ 1;
        float xv = 0.0f;
        if (tid < 32) xv = x[(row0 + tid) * LSEQ + t];

        // ======== mv1: gates1 = h1[p] @ W1^T ========
        {
            ull wr[8][4];
#pragma unroll
            for (int i = 0; i < 8; i++) {
                int ri = 8 * w + (l2 ^ (((i & 1) << 2) | (i & 2) | ((i & 4) >> 2)));
#pragma unroll
                for (int kk = 0; kk < 4; kk++)
                    wr[i][kk] = repf(W1s[ri * 128 + ln + 32 * kk]);
            }
            const float* h1p = HT1 + p * HTSZ + hoff;
#pragma unroll 1
            for (int q = 0; q < 4; q++) {
                ull A[32];
#pragma unroll
                for (int s = 0; s < 32; s++) A[s] = 0ull;
#pragma unroll
                for (int kk = 0; kk < 4; kk++) {
                    const float* hr = h1p + kk * (32 * HST) + 8 * q;
                    ull hv0 = packf2(hr[pc0], hr[pc0 + 1]);
                    ull hv1 = packf2(hr[pc1], hr[pc1 + 1]);
                    ull hv2 = packf2(hr[pc2], hr[pc2 + 1]);
                    ull hv3 = packf2(hr[pc3], hr[pc3 + 1]);
#pragma unroll
                    for (int s = 0; s < 32; s++) {
                        ull hvv = (s < 8) ? hv0 : (s < 16) ? hv1 : (s < 24) ? hv2 : hv3;
                        A[s] = ffma2(wr[s & 7][kk], hvv, A[s]);
                    }
                }
                REDUCE5(A);
                GBu[(8 * w + l2) * 17 + 4 * q + llo] = A[0];
            }
        }
        if (tid < 32) XS[tid] = xv;
        __syncthreads();

        // ======== act1 ========
        {
            ull g0 = GBu[au * 17 + ap];
            ull g1 = GBu[(16 + au) * 17 + ap];
            ull g2 = GBu[(32 + au) * 17 + ap];
            ull g3 = GBu[(48 + au) * 17 + ap];
            float xe = XS[2 * ap], xo = XS[2 * ap + 1];
            float b0 = BS1[au], b1 = BS1[16 + au], b2 = BS1[32 + au], b3 = BS1[48 + au];
            float u0 = WI1[au], u1 = WI1[16 + au], u2 = WI1[32 + au], u3 = WI1[48 + au];
            float ie = sigx (fmaf(u0, xe, flo(g0) + b0)), io_ = sigx (fmaf(u0, xo, fhi(g0) + b0));
            float fe = sigx (fmaf(u1, xe, flo(g1) + b1)), fo_ = sigx (fmaf(u1, xo, fhi(g1) + b1));
            float ge = tanhx(fmaf(u2, xe, flo(g2) + b2)), go_ = tanhx(fmaf(u2, xo, fhi(g2) + b2));
            float oe = sigx (fmaf(u3, xe, flo(g3) + b3)), oo_ = sigx (fmaf(u3, xo, fhi(g3) + b3));
            c1e = fmaf(fe, c1e, ie * ge);
            c1o = fmaf(fo_, c1o, io_ * go_);
            float he = oe * tanhx(c1e), ho = oo_ * tanhx(c1o);
            uint32_t ad = smb + 4u * (FO_HT1 + np * HTSZ + (UB + au) * HST + 2 * ap);
#pragma unroll
            for (int pcr = 0; pcr < CSIZE; pcr++) {
                st_cluster_f32(ad, pcr, he);
                st_cluster_f32(ad + 4, pcr, ho);
            }
        }
        cl_sync();   // sync_a: h1[np] complete everywhere; h2(t-1) stores complete

        // ======== readout of step t-1 ========
        if (t > 0 && tid < 32) {
            float s = blin;
#pragma unroll 8
            for (int u = 0; u < 128; u++)
                s = fmaf(HT2[u * HST + tid], WL[u], s);
            out[(row0 + tid) * LSEQ + (t - 1)] = s;
        }

        // ======== mv2: gates2 = h1[np] @ W2I^T + h2 @ W2H^T ========
        {
            ull wi[8][4], wh[8][4];
#pragma unroll
            for (int i = 0; i < 8; i++) {
                int ri = 8 * w + (l2 ^ (((i & 1) << 2) | (i & 2) | ((i & 4) >> 2)));
#pragma unroll
                for (int kk = 0; kk < 4; kk++) {
                    wi[i][kk] = repf(W2I[ri * 128 + ln + 32 * kk]);
                    wh[i][kk] = repf(W2H[ri * 128 + ln + 32 * kk]);
                }
            }
            const float* h1n = HT1 + np * HTSZ + hoff;
            const float* h2p = HT2 + hoff;
#pragma unroll 1
            for (int q = 0; q < 4; q++) {
                ull A[32];
#pragma unroll
                for (int s = 0; s < 32; s++) A[s] = 0ull;
#pragma unroll
                for (int kk = 0; kk < 4; kk++) {
                    const float* hr = h1n + kk * (32 * HST) + 8 * q;
                    ull hv0 = packf2(hr[pc0], hr[pc0 + 1]);
                    ull hv1 = packf2(hr[pc1], hr[pc1 + 1]);
                    ull hv2 = packf2(hr[pc2], hr[pc2 + 1]);
                    ull hv3 = packf2(hr[pc3], hr[pc3 + 1]);
#pragma unroll
                    for (int s = 0; s < 32; s++) {
                        ull hvv = (s < 8) ? hv0 : (s < 16) ? hv1 : (s < 24) ? hv2 : hv3;
                        A[s] = ffma2(wi[s & 7][kk], hvv, A[s]);
                    }
                }
#pragma unroll
                for (int kk = 0; kk < 4; kk++) {
                    const float* hr = h2p + kk * (32 * HST) + 8 * q;
                    ull hv0 = packf2(hr[pc0], hr[pc0 + 1]);
                    ull hv1 = packf2(hr[pc1], hr[pc1 + 1]);
                    ull hv2 = packf2(hr[pc2], hr[pc2 + 1]);
                    ull hv3 = packf2(hr[pc3], hr[pc3 + 1]);
#pragma unroll
                    for (int s = 0; s < 32; s++) {
                        ull hvv = (s < 8) ? hv0 : (s < 16) ? hv1 : (s < 24) ? hv2 : hv3;
                        A[s] = ffma2(wh[s & 7][kk], hvv, A[s]);
                    }
                }
                REDUCE5(A);
                GBu[(8 * w + l2) * 17 + 4 * q + llo] = A[0];
            }
        }
        __syncthreads();

        // ======== act2 ========
        float h2e, h2o;
        {
            ull g0 = GBu[au * 17 + ap];
            ull g1 = GBu[(16 + au) * 17 + ap];
            ull g2 = GBu[(32 + au) * 17 + ap];
            ull g3 = GBu[(48 + au) * 17 + ap];
            float b0 = BS2[au], b1 = BS2[16 + au], b2 = BS2[32 + au], b3 = BS2[48 + au];
            float ie = sigx (flo(g0) + b0), io_ = sigx (fhi(g0) + b0);
            float fe = sigx (flo(g1) + b1), fo_ = sigx (fhi(g1) + b1);
            float ge = tanhx(flo(g2) + b2), go_ = tanhx(fhi(g2) + b2);
            float oe = sigx (flo(g3) + b3), oo_ = sigx (fhi(g3) + b3);
            c2e = fmaf(fe, c2e, ie * ge);
            c2o = fmaf(fo_, c2o, io_ * go_);
            h2e = oe * tanhx(c2e);
            h2o = oo_ * tanhx(c2o);
        }
        cl_sync();   // sync_b: all mv2/readout reads of old h2 done
        {
            uint32_t ad = smb + 4u * (FO_HT2 + (UB + au) * HST + 2 * ap);
#pragma unroll
            for (int pcr = 0; pcr < CSIZE; pcr++) {
                st_cluster_f32(ad, pcr, h2e);
                st_cluster_f32(ad + 4, pcr, h2o);
            }
        }
        p = np;
    }

    // final readout (t = LSEQ-1)
    cl_sync();
    if (tid < 32) {
        float s = blin;
#pragma unroll 8
        for (int u = 0; u < 128; u++)
            s = fmaf(HT2[u * HST + tid], WL[u], s);
        out[(row0 + tid) * LSEQ + (LSEQ - 1)] = s;
    }
}

extern "C" void kernel_launch(void* const* d_in, const int* in_sizes, int n_in,
                              void* d_out, int out_size) {
    cudaFuncSetAttribute(lstm8, cudaFuncAttributeMaxDynamicSharedMemorySize, SMEM_SZ);

    const float* x     = (const float*)d_in[0];
    const float* w_ih1 = (const float*)d_in[1];
    const float* w_hh1 = (const float*)d_in[2];
    const float* b_ih1 = (const float*)d_in[3];
    const float* b_hh1 = (const float*)d_in[4];
    const float* w_ih2 = (const float*)d_in[5];
    const float* w_hh2 = (const float*)d_in[6];
    const float* b_ih2 = (const float*)d_in[7];
    const float* b_hh2 = (const float*)d_in[8];
    const float* w_lin = (const float*)d_in[9];
    const float* b_lin = (const float*)d_in[10];
    float* out = (float*)d_out;

    lstm8<<<NCTA, NT, SMEM_SZ>>>(x, w_ih1, w_hh1, b_ih1, b_hh1,
                                 w_ih2, w_hh2, b_ih2, b_hh2,
                                 w_lin, b_lin, out);
}